// round 3
// baseline (speedup 1.0000x reference)
#include <cuda_runtime.h>
#include <cuda_fp16.h>
#include <cstdint>

#define NW 16
#define NH 16
#define NSP 256          // NW*NH
#define CCH 64           // channels
#define HH 256
#define WW 256
#define HWPIX (HH * WW)
#define INVALID_DIST 1e16f

__global__ __launch_bounds__(256) void calc_assoc_kernel(
    const float* __restrict__ pix,   // [B, C, H, W]
    const float* __restrict__ sp,    // [B, C, NSP]
    const int*   __restrict__ imap,  // [B, H, W]
    float*       __restrict__ out)   // [B, 9, H, W]
{
    // 32 KB: 8 channel-octets x 256 superpixels, each entry = 8 halves (16B).
    __shared__ uint4 sh4[8 * NSP];
    __shared__ float snorm[NSP];
    __half* sh_h = reinterpret_cast<__half*>(sh4);

    const int b      = blockIdx.x >> 8;          // 256 blocks per batch
    const int pstart = (blockIdx.x & 255) << 8;  // 256 pixels per block
    const int tid    = threadIdx.x;

    // ---- Fill: transpose spb[c][n] (fp32) -> sh_h[(c>>3)*256 + n][c&7] (fp16) ----
    const float* spb = sp + (size_t)b * CCH * NSP;
    #pragma unroll
    for (int i = 0; i < (CCH * NSP) / 256; i++) {   // 64 coalesced LDG per slot
        int idx = i * 256 + tid;
        int c = idx >> 8;      // channel
        int n = idx & 255;     // superpixel
        sh_h[(((c >> 3) * NSP + n) << 3) + (c & 7)] = __float2half_rn(spb[idx]);
    }
    // snorm[n] in exact fp32: thread tid owns superpixel tid
    {
        float acc = 0.f;
        #pragma unroll
        for (int c = 0; c < CCH; c++) {
            float v = spb[c * NSP + tid];
            acc = fmaf(v, v, acc);
        }
        snorm[tid] = acc;
    }
    __syncthreads();

    // ---- Per-pixel work ----
    const int p   = pstart + tid;                  // pixel index in [0, H*W)
    const int idx = imap[(size_t)b * HWPIX + p];
    const int ix  = idx & 15;
    const int iy  = idx >> 4;

    int  nidx[9];
    bool vmask[9];
    #pragma unroll
    for (int k = 0; k < 9; k++) {
        int dy = k / 3 - 1;
        int dx = k % 3 - 1;
        int nx = ix + dx;
        int ny = iy + dy;
        vmask[k] = (nx >= 0) & (nx < NW) & (ny >= 0) & (ny < NH);
        int cx = min(max(nx, 0), NW - 1);
        int cy = min(max(ny, 0), NH - 1);
        nidx[k] = cy * NW + cx;
    }

    float acc[9];
    #pragma unroll
    for (int k = 0; k < 9; k++) acc[k] = 0.f;
    float pn = 0.f;

    const float* pp = pix + (size_t)b * CCH * HWPIX + p;

    #pragma unroll
    for (int o = 0; o < 8; o++) {   // channel octets
        float pv[8];
        #pragma unroll
        for (int j = 0; j < 8; j++) {
            pv[j] = pp[(8 * o + j) * HWPIX];     // coalesced LDG.32
            pn = fmaf(pv[j], pv[j], pn);
        }
        #pragma unroll
        for (int k = 0; k < 9; k++) {
            uint4 v = sh4[o * NSP + nidx[k]];    // LDS.128: 8 halves
            float2 f0 = __half22float2(*reinterpret_cast<__half2*>(&v.x));
            float2 f1 = __half22float2(*reinterpret_cast<__half2*>(&v.y));
            float2 f2 = __half22float2(*reinterpret_cast<__half2*>(&v.z));
            float2 f3 = __half22float2(*reinterpret_cast<__half2*>(&v.w));
            acc[k] = fmaf(pv[0], f0.x, acc[k]);
            acc[k] = fmaf(pv[1], f0.y, acc[k]);
            acc[k] = fmaf(pv[2], f1.x, acc[k]);
            acc[k] = fmaf(pv[3], f1.y, acc[k]);
            acc[k] = fmaf(pv[4], f2.x, acc[k]);
            acc[k] = fmaf(pv[5], f2.y, acc[k]);
            acc[k] = fmaf(pv[6], f3.x, acc[k]);
            acc[k] = fmaf(pv[7], f3.y, acc[k]);
        }
    }

    // ---- Epilogue: dist = pnorm + snorm - 2*dot, masked ----
    float* ob = out + (size_t)b * 9 * HWPIX + p;
    #pragma unroll
    for (int k = 0; k < 9; k++) {
        float d = pn + snorm[nidx[k]] - 2.0f * acc[k];
        ob[(size_t)k * HWPIX] = vmask[k] ? d : INVALID_DIST;
    }
}

extern "C" void kernel_launch(void* const* d_in, const int* in_sizes, int n_in,
                              void* d_out, int out_size)
{
    const float* pix = (const float*)d_in[0];
    const float* sp  = (const float*)d_in[1];
    const int*   im  = (const int*)d_in[2];
    float*       out = (float*)d_out;

    dim3 grid(4 * 256);   // B * (H*W/256)
    dim3 block(256);
    calc_assoc_kernel<<<grid, block>>>(pix, sp, im, out);
}

// round 5
// speedup vs baseline: 1.0689x; 1.0689x over previous
#include <cuda_runtime.h>
#include <cuda_fp16.h>
#include <cstdint>

#define NW 16
#define NH 16
#define NSP 256          // NW*NH
#define CCH 64           // channels
#define HH 256
#define WW 256
#define HWPIX (HH * WW)
#define INVALID_DIST 1e16f

__global__ __launch_bounds__(256, 4) void calc_assoc_kernel(
    const float* __restrict__ pix,   // [B, C, H, W]
    const float* __restrict__ sp,    // [B, C, NSP]
    const int*   __restrict__ imap,  // [B, H, W]
    float*       __restrict__ out)   // [B, 9, H, W]
{
    // 32 KB: 8 channel-octets x 256 superpixels, each entry = 8 halves (16B).
    __shared__ uint4 sh4[8 * NSP];
    __shared__ float snorm[NSP];

    const int b      = blockIdx.x >> 8;          // 256 blocks per batch
    const int pstart = (blockIdx.x & 255) << 8;  // 256 pixels per block
    const int tid    = threadIdx.x;

    // ---- Prologue: single pass over spb. Thread tid owns superpixel n = tid.
    // For each channel-octet o: 8 coalesced LDG, pack -> 1 conflict-free STS.128.
    // Exact fp32 snorm accumulated from the same registers.
    const float* spb = sp + (size_t)b * CCH * NSP;
    {
        float sn = 0.f;
        #pragma unroll
        for (int o = 0; o < 8; o++) {
            float v[8];
            #pragma unroll
            for (int j = 0; j < 8; j++) {
                v[j] = spb[(o * 8 + j) * NSP + tid];   // coalesced across tid
                sn = fmaf(v[j], v[j], sn);
            }
            uint4 pk;
            __half2 h01 = __floats2half2_rn(v[0], v[1]);
            __half2 h23 = __floats2half2_rn(v[2], v[3]);
            __half2 h45 = __floats2half2_rn(v[4], v[5]);
            __half2 h67 = __floats2half2_rn(v[6], v[7]);
            pk.x = *reinterpret_cast<unsigned*>(&h01);
            pk.y = *reinterpret_cast<unsigned*>(&h23);
            pk.z = *reinterpret_cast<unsigned*>(&h45);
            pk.w = *reinterpret_cast<unsigned*>(&h67);
            sh4[o * NSP + tid] = pk;                   // STS.128, conflict-free
        }
        snorm[tid] = sn;
    }
    __syncthreads();

    // ---- Per-pixel work ----
    const int p   = pstart + tid;                  // pixel index in [0, H*W)
    const int idx = imap[(size_t)b * HWPIX + p];
    const int ix  = idx & 15;
    const int iy  = idx >> 4;

    int  nidx[9];
    bool vmask[9];
    #pragma unroll
    for (int k = 0; k < 9; k++) {
        int dy = k / 3 - 1;
        int dx = k % 3 - 1;
        int nx = ix + dx;
        int ny = iy + dy;
        vmask[k] = (nx >= 0) & (nx < NW) & (ny >= 0) & (ny < NH);
        int cx = min(max(nx, 0), NW - 1);
        int cy = min(max(ny, 0), NH - 1);
        nidx[k] = cy * NW + cx;
    }

    float acc[9];
    #pragma unroll
    for (int k = 0; k < 9; k++) acc[k] = 0.f;
    float pn = 0.f;

    const float* pp = pix + (size_t)b * CCH * HWPIX + p;

    #pragma unroll
    for (int o = 0; o < 8; o++) {   // channel octets
        float pv[8];
        #pragma unroll
        for (int j = 0; j < 8; j++) {
            pv[j] = pp[(8 * o + j) * HWPIX];     // coalesced LDG.32
            pn = fmaf(pv[j], pv[j], pn);
        }
        #pragma unroll
        for (int k = 0; k < 9; k++) {
            uint4 v = sh4[o * NSP + nidx[k]];    // LDS.128: 8 halves
            float2 f0 = __half22float2(*reinterpret_cast<__half2*>(&v.x));
            float2 f1 = __half22float2(*reinterpret_cast<__half2*>(&v.y));
            float2 f2 = __half22float2(*reinterpret_cast<__half2*>(&v.z));
            float2 f3 = __half22float2(*reinterpret_cast<__half2*>(&v.w));
            acc[k] = fmaf(pv[0], f0.x, acc[k]);
            acc[k] = fmaf(pv[1], f0.y, acc[k]);
            acc[k] = fmaf(pv[2], f1.x, acc[k]);
            acc[k] = fmaf(pv[3], f1.y, acc[k]);
            acc[k] = fmaf(pv[4], f2.x, acc[k]);
            acc[k] = fmaf(pv[5], f2.y, acc[k]);
            acc[k] = fmaf(pv[6], f3.x, acc[k]);
            acc[k] = fmaf(pv[7], f3.y, acc[k]);
        }
    }

    // ---- Epilogue: dist = pnorm + snorm - 2*dot, masked ----
    float* ob = out + (size_t)b * 9 * HWPIX + p;
    #pragma unroll
    for (int k = 0; k < 9; k++) {
        float d = pn + snorm[nidx[k]] - 2.0f * acc[k];
        ob[(size_t)k * HWPIX] = vmask[k] ? d : INVALID_DIST;
    }
}

extern "C" void kernel_launch(void* const* d_in, const int* in_sizes, int n_in,
                              void* d_out, int out_size)
{
    const float* pix = (const float*)d_in[0];
    const float* sp  = (const float*)d_in[1];
    const int*   im  = (const int*)d_in[2];
    float*       out = (float*)d_out;

    dim3 grid(4 * 256);   // B * (H*W/256)
    dim3 block(256);
    calc_assoc_kernel<<<grid, block>>>(pix, sp, im, out);
}

// round 6
// speedup vs baseline: 1.3508x; 1.2636x over previous
#include <cuda_runtime.h>
#include <cuda_fp16.h>
#include <cstdint>

#define NW 16
#define NH 16
#define NSP 256          // NW*NH
#define CCH 64           // channels
#define HH 256
#define WW 256
#define HWPIX (HH * WW)
#define INVALID_DIST 1e16f

// Pack two fp32 -> one u16 holding two e4m3 (lo = a, hi = b).
__device__ __forceinline__ unsigned short pack_e4m3x2(float a, float b) {
    unsigned short r;
    // PTX: cvt d, X, Y -> d.hi = X, d.lo = Y
    asm("cvt.rn.satfinite.e4m3x2.f32 %0, %1, %2;" : "=h"(r) : "f"(b), "f"(a));
    return r;
}
// Unpack u16 (two e4m3) -> half2 (.x = lo, .y = hi).
__device__ __forceinline__ __half2 e4m3x2_to_half2(unsigned short v) {
    __half2 h;
    asm("cvt.rn.f16x2.e4m3x2 %0, %1;" : "=r"(*reinterpret_cast<unsigned*>(&h)) : "h"(v));
    return h;
}

__global__ __launch_bounds__(256, 4) void calc_assoc_kernel(
    const float* __restrict__ pix,   // [B, C, H, W]
    const float* __restrict__ sp,    // [B, C, NSP]
    const int*   __restrict__ imap,  // [B, H, W]
    float*       __restrict__ out)   // [B, 9, H, W]
{
    // 16 KB: 4 channel-hexes x 256 superpixels, each entry = 16 e4m3 (16B).
    __shared__ uint4 sh4[4 * NSP];
    __shared__ float snorm[NSP];

    const int b      = blockIdx.x >> 8;          // 256 blocks per batch
    const int pstart = (blockIdx.x & 255) << 8;  // 256 pixels per block
    const int tid    = threadIdx.x;

    // ---- Prologue: thread tid owns superpixel n = tid. Single pass:
    // 16 coalesced LDG per hex -> pack 16 e4m3 -> 1 conflict-free STS.128.
    // Exact fp32 snorm from the same registers.
    const float* spb = sp + (size_t)b * CCH * NSP;
    {
        float sn = 0.f;
        #pragma unroll
        for (int h = 0; h < 4; h++) {
            float v[16];
            #pragma unroll
            for (int j = 0; j < 16; j++) {
                v[j] = spb[(h * 16 + j) * NSP + tid];   // coalesced across tid
                sn = fmaf(v[j], v[j], sn);
            }
            uint4 pk;
            pk.x = (unsigned)pack_e4m3x2(v[0],  v[1])  | ((unsigned)pack_e4m3x2(v[2],  v[3])  << 16);
            pk.y = (unsigned)pack_e4m3x2(v[4],  v[5])  | ((unsigned)pack_e4m3x2(v[6],  v[7])  << 16);
            pk.z = (unsigned)pack_e4m3x2(v[8],  v[9])  | ((unsigned)pack_e4m3x2(v[10], v[11]) << 16);
            pk.w = (unsigned)pack_e4m3x2(v[12], v[13]) | ((unsigned)pack_e4m3x2(v[14], v[15]) << 16);
            sh4[h * NSP + tid] = pk;                    // STS.128, conflict-free
        }
        snorm[tid] = sn;
    }
    __syncthreads();

    // ---- Per-pixel work ----
    const int p   = pstart + tid;                  // pixel index in [0, H*W)
    const int idx = imap[(size_t)b * HWPIX + p];
    const int ix  = idx & 15;
    const int iy  = idx >> 4;

    int nidx[9];
    int vbits = 0;
    #pragma unroll
    for (int k = 0; k < 9; k++) {
        int dy = k / 3 - 1;
        int dx = k % 3 - 1;
        int nx = ix + dx;
        int ny = iy + dy;
        if ((nx >= 0) & (nx < NW) & (ny >= 0) & (ny < NH)) vbits |= (1 << k);
        int cx = min(max(nx, 0), NW - 1);
        int cy = min(max(ny, 0), NH - 1);
        nidx[k] = cy * NW + cx;
    }

    __half2 acc2[9];
    #pragma unroll
    for (int k = 0; k < 9; k++) acc2[k] = __floats2half2_rn(0.f, 0.f);
    float pn = 0.f;

    const float* pp = pix + (size_t)b * CCH * HWPIX + p;

    #pragma unroll
    for (int h = 0; h < 4; h++) {   // channel hexes (16 channels each)
        float f[16];
        #pragma unroll
        for (int j = 0; j < 16; j++) {
            f[j] = pp[(16 * h + j) * HWPIX];       // coalesced LDG.32
            pn = fmaf(f[j], f[j], pn);
        }
        __half2 pv2[8];
        #pragma unroll
        for (int j = 0; j < 8; j++)
            pv2[j] = __floats2half2_rn(f[2 * j], f[2 * j + 1]);

        #pragma unroll
        for (int k = 0; k < 9; k++) {
            uint4 v = sh4[h * NSP + nidx[k]];      // LDS.128: 16 e4m3
            __half2 a = acc2[k];
            a = __hfma2(pv2[0], e4m3x2_to_half2((unsigned short)(v.x      )), a);
            a = __hfma2(pv2[1], e4m3x2_to_half2((unsigned short)(v.x >> 16)), a);
            a = __hfma2(pv2[2], e4m3x2_to_half2((unsigned short)(v.y      )), a);
            a = __hfma2(pv2[3], e4m3x2_to_half2((unsigned short)(v.y >> 16)), a);
            a = __hfma2(pv2[4], e4m3x2_to_half2((unsigned short)(v.z      )), a);
            a = __hfma2(pv2[5], e4m3x2_to_half2((unsigned short)(v.z >> 16)), a);
            a = __hfma2(pv2[6], e4m3x2_to_half2((unsigned short)(v.w      )), a);
            a = __hfma2(pv2[7], e4m3x2_to_half2((unsigned short)(v.w >> 16)), a);
            acc2[k] = a;
        }
    }

    // ---- Epilogue: dist = pnorm + snorm - 2*dot, masked ----
    float* ob = out + (size_t)b * 9 * HWPIX + p;
    #pragma unroll
    for (int k = 0; k < 9; k++) {
        float2 d2 = __half22float2(acc2[k]);
        float dot = d2.x + d2.y;
        float d = pn + snorm[nidx[k]] - 2.0f * dot;
        ob[(size_t)k * HWPIX] = (vbits >> k) & 1 ? d : INVALID_DIST;
    }
}

extern "C" void kernel_launch(void* const* d_in, const int* in_sizes, int n_in,
                              void* d_out, int out_size)
{
    const float* pix = (const float*)d_in[0];
    const float* sp  = (const float*)d_in[1];
    const int*   im  = (const int*)d_in[2];
    float*       out = (float*)d_out;

    dim3 grid(4 * 256);   // B * (H*W/256)
    dim3 block(256);
    calc_assoc_kernel<<<grid, block>>>(pix, sp, im, out);
}